// round 7
// baseline (speedup 1.0000x reference)
#include <cuda_runtime.h>

// SlidingWindow: k,v (1, 2048, 16, 64) fp32, W=64
// out = concat(k_win, v_win), each (1, 2048, 16, 64, 64) fp32 layout [t][h][w][d]
// out_k[t,h,w,d] = (w < min(t+1,W)) ? k[max(0,t+1-W)+w, h, d] : 0
//
// 256-bit (float8) granularity: sm_103a supports ld.global.v8.f32 / st.global.v8.f32.
// Halves global-access instruction count + L1tex wavefront dispatches vs float4.

#define H_DIM 16
#define W_DIM 64

// per-tensor float8 count: 2048*16*64*64/8 = 16,777,216
#define N8 16777216LL

#define TPB 256
#define ILP 4
// per-block float8s = 1024; one t-slice = 16*64*8 = 8192 float8s = 8 blocks.
// blocks with blockIdx >= 63*8 = 504 cover t >= 63 -> always full window.
#define FIRST_ALL_VALID_BLOCK 504

__device__ __forceinline__ void ldg256_nc(const float* p, float* r) {
    asm volatile("ld.global.nc.v8.f32 {%0,%1,%2,%3,%4,%5,%6,%7}, [%8];"
        : "=f"(r[0]), "=f"(r[1]), "=f"(r[2]), "=f"(r[3]),
          "=f"(r[4]), "=f"(r[5]), "=f"(r[6]), "=f"(r[7])
        : "l"(p));
}

__device__ __forceinline__ void stg256_cs(float* p, const float* r) {
    asm volatile("st.global.cs.v8.f32 [%0], {%1,%2,%3,%4,%5,%6,%7,%8};"
        :: "l"(p),
           "f"(r[0]), "f"(r[1]), "f"(r[2]), "f"(r[3]),
           "f"(r[4]), "f"(r[5]), "f"(r[6]), "f"(r[7])
        : "memory");
}

__global__ __launch_bounds__(TPB) void sliding_window_kernel(
    const float* __restrict__ k,
    const float* __restrict__ v,
    float* __restrict__ out)   // floats: [0, N8*8) = k_win, [N8*8, 2*N8*8) = v_win
{
    // block-strided ILP at float8 granularity: thread tid handles float8
    // indices blk + j*TPB -> every LDG.256/STG.256 is a fully-coalesced 1KB
    // contiguous warp transaction.
    const long long blk = (long long)blockIdx.x * (TPB * ILP) + threadIdx.x;

    float kk[ILP][8], vv[ILP][8];
    const float* ksrc[ILP];
    const float* vsrc[ILP];

    if (blockIdx.x >= FIRST_ALL_VALID_BLOCK) {
        // fast path: t >= 63, window always full, no predication.
#pragma unroll
        for (int j = 0; j < ILP; j++) {
            const long long i8 = blk + (long long)j * TPB;
            const int d8 = (int)(i8 & 7);
            const int w  = (int)((i8 >> 3) & 63);
            const int h  = (int)((i8 >> 9) & 15);
            const int t  = (int)(i8 >> 13);
            const int src_t = t + 1 - W_DIM + w;
            const long long src_f = (((long long)src_t * H_DIM + h) << 6) + (d8 << 3);
            ksrc[j] = k + src_f;
            vsrc[j] = v + src_f;
        }
#pragma unroll
        for (int j = 0; j < ILP; j++) ldg256_nc(ksrc[j], kk[j]);
#pragma unroll
        for (int j = 0; j < ILP; j++) ldg256_nc(vsrc[j], vv[j]);
    } else {
        // slow path: t < 63, window may be partial (zero-fill; start = 0).
        bool valid[ILP];
#pragma unroll
        for (int j = 0; j < ILP; j++) {
            const long long i8 = blk + (long long)j * TPB;
            const int d8 = (int)(i8 & 7);
            const int w  = (int)((i8 >> 3) & 63);
            const int h  = (int)((i8 >> 9) & 15);
            const int t  = (int)(i8 >> 13);
            valid[j] = (w <= t);
            const long long src_f = (((long long)w * H_DIM + h) << 6) + (d8 << 3);
            ksrc[j] = k + src_f;
            vsrc[j] = v + src_f;
        }
#pragma unroll
        for (int j = 0; j < ILP; j++) {
            if (valid[j]) {
                ldg256_nc(ksrc[j], kk[j]);
                ldg256_nc(vsrc[j], vv[j]);
            } else {
#pragma unroll
                for (int e = 0; e < 8; e++) { kk[j][e] = 0.f; vv[j][e] = 0.f; }
            }
        }
    }

#pragma unroll
    for (int j = 0; j < ILP; j++)
        stg256_cs(out + ((blk + (long long)j * TPB) << 3), kk[j]);
#pragma unroll
    for (int j = 0; j < ILP; j++)
        stg256_cs(out + ((blk + (long long)j * TPB + N8) << 3), vv[j]);
}

extern "C" void kernel_launch(void* const* d_in, const int* in_sizes, int n_in,
                              void* d_out, int out_size) {
    const float* k = (const float*)d_in[0];
    const float* v = (const float*)d_in[1];
    float* out = (float*)d_out;

    const int blocks = (int)(N8 / (TPB * ILP));  // 16384
    sliding_window_kernel<<<blocks, TPB>>>(k, v, out);
}

// round 8
// speedup vs baseline: 1.0697x; 1.0697x over previous
#include <cuda_runtime.h>

// SlidingWindow: k,v (1, 2048, 16, 64) fp32, W=64
// out = concat(k_win, v_win), each (1, 2048, 16, 64, 64) fp32 layout [t][h][w][d]
// out_k[t,h,w,d] = (w < min(t+1,W)) ? k[max(0,t+1-W)+w, h, d] : 0
//
// Converged configuration (best measured 145.9us ~= 7.6 TB/s effective, ~95% of
// HBM3e spec on the mandatory 1.07GB write stream):
//  - float4 granularity, fully-coalesced block-strided ILP=8 (512B/warp/instr)
//  - fast/slow block split: 96.9% of blocks skip window predication entirely
//  - __stcs evict-first stores on the write-once output stream

#define H_DIM 16
#define W_DIM 64

// per-tensor float4 count: 2048*16*64*64/4 = 33,554,432
#define N4 33554432LL

#define TPB 256
#define ILP 8
// one t-slice = 16*64*16 = 16384 float4s = 8 blocks of TPB*ILP=2048.
// blocks with blockIdx >= 63*8 = 504 cover t >= 63 -> always full window.
#define FIRST_ALL_VALID_BLOCK 504

__global__ __launch_bounds__(TPB) void sliding_window_kernel(
    const float4* __restrict__ k4,
    const float4* __restrict__ v4,
    float4* __restrict__ out4)   // [0, N4) = k_win, [N4, 2N4) = v_win
{
    const long long blk = (long long)blockIdx.x * (TPB * ILP) + threadIdx.x;

    long long src[ILP];
    float4 kk[ILP], vv[ILP];

    if (blockIdx.x >= FIRST_ALL_VALID_BLOCK) {
        // fast path: t >= 63, window always full, no predication.
#pragma unroll
        for (int j = 0; j < ILP; j++) {
            const long long i = blk + (long long)j * TPB;
            const int d4 = (int)(i & 15);
            const int w  = (int)((i >> 4) & 63);
            const int h  = (int)((i >> 10) & 15);
            const int t  = (int)(i >> 14);
            const int src_t = t + 1 - W_DIM + w;
            src[j] = (((long long)src_t * H_DIM + h) << 4) + d4;
        }
#pragma unroll
        for (int j = 0; j < ILP; j++) kk[j] = __ldg(&k4[src[j]]);
#pragma unroll
        for (int j = 0; j < ILP; j++) vv[j] = __ldg(&v4[src[j]]);
    } else {
        // slow path: t < 63, window may be partial (zero-fill; start = 0).
        const float4 z = make_float4(0.f, 0.f, 0.f, 0.f);
        bool valid[ILP];
#pragma unroll
        for (int j = 0; j < ILP; j++) {
            const long long i = blk + (long long)j * TPB;
            const int d4 = (int)(i & 15);
            const int w  = (int)((i >> 4) & 63);
            const int h  = (int)((i >> 10) & 15);
            const int t  = (int)(i >> 14);
            valid[j] = (w <= t);
            src[j] = (((long long)w * H_DIM + h) << 4) + d4;
        }
#pragma unroll
        for (int j = 0; j < ILP; j++) kk[j] = valid[j] ? __ldg(&k4[src[j]]) : z;
#pragma unroll
        for (int j = 0; j < ILP; j++) vv[j] = valid[j] ? __ldg(&v4[src[j]]) : z;
    }

#pragma unroll
    for (int j = 0; j < ILP; j++)
        __stcs(&out4[blk + (long long)j * TPB], kk[j]);       // evict-first stream
#pragma unroll
    for (int j = 0; j < ILP; j++)
        __stcs(&out4[blk + (long long)j * TPB + N4], vv[j]);
}

extern "C" void kernel_launch(void* const* d_in, const int* in_sizes, int n_in,
                              void* d_out, int out_size) {
    const float4* k4 = (const float4*)d_in[0];
    const float4* v4 = (const float4*)d_in[1];
    float4* out4 = (float4*)d_out;

    const int blocks = (int)(N4 / (TPB * ILP));  // 16384
    sliding_window_kernel<<<blocks, TPB>>>(k4, v4, out4);
}